// round 2
// baseline (speedup 1.0000x reference)
#include <cuda_runtime.h>

#define BATCH 32
#define CDIM  256
#define LDIM  1024

// Scratch: softmax probabilities P[B][L][L] fp32 (128 MiB) + dense bias [L][L].
__device__ float d_P[(size_t)BATCH * LDIM * LDIM];
__device__ float d_bias[(size_t)LDIM * LDIM];

// ---------------------------------------------------------------------------
// Kernel 0: expand bias_table[rel_index] -> dense [L,L]
// ---------------------------------------------------------------------------
__global__ void bias_kernel(const float* __restrict__ table,
                            const int* __restrict__ ridx) {
    int i = blockIdx.x * blockDim.x + threadIdx.x;  // grid covers L*L exactly
    d_bias[i] = table[ridx[i]];
}

// ---------------------------------------------------------------------------
// Kernel 1: scores = Q^T K + bias, softmax over j, write P.
// CTA: 32 query rows x full 1024 keys. 512 threads = 4 (tr) x 128 (tc).
// Thread tile: 8 rows x 8 cols (cols strided by 128).
// C reduced in chunks of 32 through smem.
// ---------------------------------------------------------------------------
#define ROWS 32
#define CK   32
#define T1   512

__global__ void __launch_bounds__(T1) scores_kernel(const float* __restrict__ q,
                                                    const float* __restrict__ k) {
    extern __shared__ float smem[];
    float* ks  = smem;                 // [CK][LDIM]
    float* qs  = smem + CK * LDIM;     // [ROWS][33] padded
    float* red = qs + ROWS * 33;       // [ROWS][4]

    const int b   = blockIdx.y;
    const int i0  = blockIdx.x * ROWS;
    const int tid = threadIdx.x;
    const int tr  = tid >> 7;          // 0..3
    const int tc  = tid & 127;         // 0..127
    const int lane = tid & 31;
    const int wsub = tc >> 5;          // warp within the 128-thread col group

    const float* qb = q + (size_t)b * CDIM * LDIM;
    const float* kb = k + (size_t)b * CDIM * LDIM;

    float acc[8][8];
#pragma unroll
    for (int a = 0; a < 8; a++)
#pragma unroll
        for (int d = 0; d < 8; d++) acc[a][d] = 0.f;

    for (int c0 = 0; c0 < CDIM; c0 += CK) {
        // K chunk [CK][1024], fully coalesced float4
        const float4* ksrc = (const float4*)(kb + (size_t)c0 * LDIM);
        float4* kdst = (float4*)ks;
        for (int idx = tid; idx < CK * LDIM / 4; idx += T1) kdst[idx] = ksrc[idx];
        // Q chunk [ROWS][CK] -> qs[r][cc]
        for (int idx = tid; idx < ROWS * CK; idx += T1) {
            int cc = idx >> 5;         // 0..31
            int r  = idx & 31;
            qs[r * 33 + cc] = qb[(size_t)(c0 + cc) * LDIM + i0 + r];
        }
        __syncthreads();

#pragma unroll 2
        for (int cc = 0; cc < CK; cc++) {
            float qreg[8], kreg[8];
#pragma unroll
            for (int rr = 0; rr < 8; rr++) qreg[rr] = qs[(tr * 8 + rr) * 33 + cc];
#pragma unroll
            for (int jj = 0; jj < 8; jj++) kreg[jj] = ks[cc * LDIM + tc + 128 * jj];
#pragma unroll
            for (int rr = 0; rr < 8; rr++)
#pragma unroll
                for (int jj = 0; jj < 8; jj++)
                    acc[rr][jj] = fmaf(qreg[rr], kreg[jj], acc[rr][jj]);
        }
        __syncthreads();
    }

    // add bias
#pragma unroll
    for (int rr = 0; rr < 8; rr++) {
        int row = i0 + tr * 8 + rr;
        const float* brow = d_bias + (size_t)row * LDIM;
#pragma unroll
        for (int jj = 0; jj < 8; jj++) acc[rr][jj] += brow[tc + 128 * jj];
    }

    // ---- row max (across 128 tc threads = 4 warps) ----
#pragma unroll
    for (int rr = 0; rr < 8; rr++) {
        float m = acc[rr][0];
#pragma unroll
        for (int jj = 1; jj < 8; jj++) m = fmaxf(m, acc[rr][jj]);
#pragma unroll
        for (int o = 16; o > 0; o >>= 1) m = fmaxf(m, __shfl_xor_sync(0xffffffffu, m, o));
        if (lane == 0) red[(tr * 8 + rr) * 4 + wsub] = m;
    }
    __syncthreads();
    float mrow[8];
#pragma unroll
    for (int rr = 0; rr < 8; rr++) {
        const float* r4 = red + (tr * 8 + rr) * 4;
        mrow[rr] = fmaxf(fmaxf(r4[0], r4[1]), fmaxf(r4[2], r4[3]));
    }
    __syncthreads();  // protect red before reuse

    // ---- exp + row sum ----
#pragma unroll
    for (int rr = 0; rr < 8; rr++) {
        float s = 0.f;
#pragma unroll
        for (int jj = 0; jj < 8; jj++) {
            float p = __expf(acc[rr][jj] - mrow[rr]);
            acc[rr][jj] = p;
            s += p;
        }
#pragma unroll
        for (int o = 16; o > 0; o >>= 1) s += __shfl_xor_sync(0xffffffffu, s, o);
        if (lane == 0) red[(tr * 8 + rr) * 4 + wsub] = s;
    }
    __syncthreads();

    float* Pb = d_P + ((size_t)b * LDIM + i0) * LDIM;
#pragma unroll
    for (int rr = 0; rr < 8; rr++) {
        const float* r4 = red + (tr * 8 + rr) * 4;
        float inv = 1.0f / (r4[0] + r4[1] + r4[2] + r4[3]);
        float* prow = Pb + (size_t)(tr * 8 + rr) * LDIM;
#pragma unroll
        for (int jj = 0; jj < 8; jj++) prow[tc + 128 * jj] = acc[rr][jj] * inv;
    }
}

// ---------------------------------------------------------------------------
// Kernel 2: V = P @ v^T, SD = P @ std^T (fused, shared P tile).
// CTA tile: 128 i x 64 c. 256 threads = 16 (it) x 16 (ct).
// Thread tile: 8 i x 4 c, two accumulator sets.
// ---------------------------------------------------------------------------
#define JT 32
#define T2 256

__global__ void __launch_bounds__(T2) out_kernel(const float* __restrict__ v,
                                                 const float* __restrict__ sd,
                                                 float* __restrict__ out) {
    __shared__ float ps[JT][132];
    __shared__ float vs[JT][68];
    __shared__ float ss[JT][68];

    const int b  = blockIdx.z;
    const int i0 = blockIdx.x * 128;
    const int c0 = blockIdx.y * 64;
    const int tid = threadIdx.x;
    const int it = tid & 15;
    const int ct = tid >> 4;

    const float* Pb = d_P + ((size_t)b * LDIM + i0) * LDIM;
    const float* vb = v  + ((size_t)b * CDIM + c0) * LDIM;
    const float* sb = sd + ((size_t)b * CDIM + c0) * LDIM;

    float aV[8][4], aS[8][4];
#pragma unroll
    for (int a = 0; a < 8; a++)
#pragma unroll
        for (int d = 0; d < 4; d++) { aV[a][d] = 0.f; aS[a][d] = 0.f; }

    for (int j0 = 0; j0 < LDIM; j0 += JT) {
        // P tile 128 x JT -> transposed ps[jj][i]
        for (int idx = tid; idx < 128 * (JT / 4); idx += T2) {
            int i  = idx >> 3;
            int j4 = (idx & 7) * 4;
            float4 t = *(const float4*)(Pb + (size_t)i * LDIM + j0 + j4);
            ps[j4 + 0][i] = t.x; ps[j4 + 1][i] = t.y;
            ps[j4 + 2][i] = t.z; ps[j4 + 3][i] = t.w;
        }
        // v / std tiles 64 x JT -> transposed
        for (int idx = tid; idx < 64 * (JT / 4); idx += T2) {
            int c  = idx >> 3;
            int j4 = (idx & 7) * 4;
            float4 t = *(const float4*)(vb + (size_t)c * LDIM + j0 + j4);
            vs[j4 + 0][c] = t.x; vs[j4 + 1][c] = t.y;
            vs[j4 + 2][c] = t.z; vs[j4 + 3][c] = t.w;
            float4 u = *(const float4*)(sb + (size_t)c * LDIM + j0 + j4);
            ss[j4 + 0][c] = u.x; ss[j4 + 1][c] = u.y;
            ss[j4 + 2][c] = u.z; ss[j4 + 3][c] = u.w;
        }
        __syncthreads();

#pragma unroll 2
        for (int jj = 0; jj < JT; jj++) {
            float pr[8], vr[4], sr[4];
#pragma unroll
            for (int ii = 0; ii < 8; ii++) pr[ii] = ps[jj][it + 16 * ii];
#pragma unroll
            for (int cc = 0; cc < 4; cc++) { vr[cc] = vs[jj][ct + 16 * cc];
                                             sr[cc] = ss[jj][ct + 16 * cc]; }
#pragma unroll
            for (int ii = 0; ii < 8; ii++)
#pragma unroll
                for (int cc = 0; cc < 4; cc++) {
                    aV[ii][cc] = fmaf(pr[ii], vr[cc], aV[ii][cc]);
                    aS[ii][cc] = fmaf(pr[ii], sr[cc], aS[ii][cc]);
                }
        }
        __syncthreads();
    }

    const size_t base  = (size_t)b * CDIM * LDIM;
    const size_t sdoff = (size_t)BATCH * CDIM * LDIM;  // 8388608
#pragma unroll
    for (int ii = 0; ii < 8; ii++) {
        int i = i0 + it + 16 * ii;
#pragma unroll
        for (int cc = 0; cc < 4; cc++) {
            int c = c0 + ct + 16 * cc;
            size_t o = base + (size_t)c * LDIM + i;
            out[o]         = aV[ii][cc];
            out[o + sdoff] = aS[ii][cc];
        }
    }
}

// ---------------------------------------------------------------------------
extern "C" void kernel_launch(void* const* d_in, const int* in_sizes, int n_in,
                              void* d_out, int out_size) {
    const float* q     = (const float*)d_in[0];
    const float* k     = (const float*)d_in[1];
    const float* v     = (const float*)d_in[2];
    const float* sd    = (const float*)d_in[3];
    const float* table = (const float*)d_in[4];
    const int*   ridx  = (const int*)d_in[5];
    float* out = (float*)d_out;

    const int smem1 = (CK * LDIM + ROWS * 33 + ROWS * 4) * (int)sizeof(float); // ~135.8 KB
    cudaFuncSetAttribute(scores_kernel, cudaFuncAttributeMaxDynamicSharedMemorySize, smem1);

    bias_kernel<<<(LDIM * LDIM) / 256, 256>>>(table, ridx);
    scores_kernel<<<dim3(LDIM / ROWS, BATCH), T1, smem1>>>(q, k);
    out_kernel<<<dim3(LDIM / 128, CDIM / 64, BATCH), T2>>>(v, sd, out);
}

// round 3
// speedup vs baseline: 1.7484x; 1.7484x over previous
#include <cuda_runtime.h>

#define BATCH 32
#define CDIM  256
#define LDIM  1024

// Scratch: softmax probabilities P[B][L][L] fp32 (128 MiB) + dense bias [L][L].
__device__ float d_P[(size_t)BATCH * LDIM * LDIM];
__device__ float d_bias[(size_t)LDIM * LDIM];

// ---------------------------------------------------------------------------
// tf32 mma.sync helpers
// ---------------------------------------------------------------------------
__device__ __forceinline__ void mma8(float* c,
                                     unsigned a0, unsigned a1, unsigned a2, unsigned a3,
                                     unsigned b0, unsigned b1) {
    asm volatile(
        "mma.sync.aligned.m16n8k8.row.col.f32.tf32.tf32.f32 "
        "{%0,%1,%2,%3}, {%4,%5,%6,%7}, {%8,%9}, {%0,%1,%2,%3};\n"
        : "+f"(c[0]), "+f"(c[1]), "+f"(c[2]), "+f"(c[3])
        : "r"(a0), "r"(a1), "r"(a2), "r"(a3), "r"(b0), "r"(b1));
}

__device__ __forceinline__ unsigned tf32_hi(float x) {
    return __float_as_uint(x) & 0xffffe000u;
}
__device__ __forceinline__ unsigned tf32_lo(float x, unsigned hi) {
    return __float_as_uint(x - __uint_as_float(hi));
}
__device__ __forceinline__ unsigned tf32_rna(float x) {
    unsigned r;
    asm("cvt.rna.tf32.f32 %0, %1;" : "=r"(r) : "f"(x));
    return r;
}

// ---------------------------------------------------------------------------
// Kernel 0: expand bias_table[rel_index] -> dense [L,L]
// ---------------------------------------------------------------------------
__global__ void bias_kernel(const float* __restrict__ table,
                            const int* __restrict__ ridx) {
    int i = blockIdx.x * blockDim.x + threadIdx.x;
    d_bias[i] = table[ridx[i]];
}

// ---------------------------------------------------------------------------
// Kernel 1: scores = Q^T K + bias (tf32x3 split), softmax over j, write P.
// CTA: 32 i-rows x 1024 j (full row). 512 threads = 16 warps.
// Warp tile: 32i x 64j = 2 i-tiles x 8 j-tiles of m16n8. C chunked by 32.
// smem: ks[32][1032] (pad so B-frag LDS conflict-free), qs[32][36].
// ---------------------------------------------------------------------------
#define T1 512
#define KSTRIDE 1032
#define QSTRIDE 36

__global__ void __launch_bounds__(T1)
scores_mma_kernel(const float* __restrict__ q, const float* __restrict__ k) {
    extern __shared__ float smem[];
    float* ks  = smem;                       // [32][1032]
    float* qs  = smem + 32 * KSTRIDE;        // [32][36]
    float* red = qs + 32 * QSTRIDE;          // [32][16]

    const int b    = blockIdx.y;
    const int i0   = blockIdx.x * 32;
    const int tid  = threadIdx.x;
    const int warp = tid >> 5;
    const int lane = tid & 31;
    const int g    = lane >> 2;              // group row 0..7
    const int tig  = lane & 3;               // thread-in-group
    const int j0w  = warp * 64;

    const float* qb = q + (size_t)b * CDIM * LDIM;
    const float* kb = k + (size_t)b * CDIM * LDIM;

    float acc[2][8][4];
#pragma unroll
    for (int it = 0; it < 2; it++)
#pragma unroll
        for (int jt = 0; jt < 8; jt++)
#pragma unroll
            for (int f = 0; f < 4; f++) acc[it][jt][f] = 0.f;

    for (int c0 = 0; c0 < CDIM; c0 += 32) {
        // K chunk [32][1024] -> ks, coalesced float4
#pragma unroll
        for (int t = 0; t < 16; t++) {
            int idx = tid + t * T1;
            int row = idx >> 8;
            int col = (idx & 255) << 2;
            *(float4*)(ks + row * KSTRIDE + col) =
                *(const float4*)(kb + (size_t)(c0 + row) * LDIM + col);
        }
        // Q chunk: qs[r][cc] = q[c0+cc][i0+r]
#pragma unroll
        for (int t = 0; t < 2; t++) {
            int idx = tid + t * T1;
            int cc = idx >> 5;
            int r  = idx & 31;
            qs[r * QSTRIDE + cc] = qb[(size_t)(c0 + cc) * LDIM + i0 + r];
        }
        __syncthreads();

#pragma unroll
        for (int kk = 0; kk < 32; kk += 8) {
            // A fragments (hi/lo split)
            unsigned ah[2][4], al[2][4];
#pragma unroll
            for (int it = 0; it < 2; it++) {
                int base = (it * 16 + g) * QSTRIDE + kk + tig;
                float a0 = qs[base];
                float a1 = qs[base + 8 * QSTRIDE];
                float a2 = qs[base + 4];
                float a3 = qs[base + 8 * QSTRIDE + 4];
                ah[it][0] = tf32_hi(a0); al[it][0] = tf32_lo(a0, ah[it][0]);
                ah[it][1] = tf32_hi(a1); al[it][1] = tf32_lo(a1, ah[it][1]);
                ah[it][2] = tf32_hi(a2); al[it][2] = tf32_lo(a2, ah[it][2]);
                ah[it][3] = tf32_hi(a3); al[it][3] = tf32_lo(a3, ah[it][3]);
            }
#pragma unroll
            for (int jt = 0; jt < 8; jt++) {
                int jcol = j0w + jt * 8 + g;
                float b0 = ks[(kk + tig) * KSTRIDE + jcol];
                float b1 = ks[(kk + tig + 4) * KSTRIDE + jcol];
                unsigned bh0 = tf32_hi(b0), bh1 = tf32_hi(b1);
                unsigned bl0 = tf32_lo(b0, bh0), bl1 = tf32_lo(b1, bh1);
#pragma unroll
                for (int it = 0; it < 2; it++) {
                    mma8(acc[it][jt], ah[it][0], ah[it][1], ah[it][2], ah[it][3], bh0, bh1);
                    mma8(acc[it][jt], ah[it][0], ah[it][1], ah[it][2], ah[it][3], bl0, bl1);
                    mma8(acc[it][jt], al[it][0], al[it][1], al[it][2], al[it][3], bh0, bh1);
                }
            }
        }
        __syncthreads();
    }

    // ---- add bias ----
#pragma unroll
    for (int it = 0; it < 2; it++)
#pragma unroll
        for (int rr = 0; rr < 2; rr++) {
            int rowl = it * 16 + g + rr * 8;
            const float* brow = d_bias + (size_t)(i0 + rowl) * LDIM + j0w + 2 * tig;
#pragma unroll
            for (int jt = 0; jt < 8; jt++) {
                float2 bv = *(const float2*)(brow + jt * 8);
                acc[it][jt][rr * 2]     += bv.x;
                acc[it][jt][rr * 2 + 1] += bv.y;
            }
        }

    // ---- row max over full 1024 j (16 warps share rows) ----
    float mrow[2][2];
#pragma unroll
    for (int it = 0; it < 2; it++)
#pragma unroll
        for (int rr = 0; rr < 2; rr++) {
            float m = -3.4e38f;
#pragma unroll
            for (int jt = 0; jt < 8; jt++) {
                m = fmaxf(m, acc[it][jt][rr * 2]);
                m = fmaxf(m, acc[it][jt][rr * 2 + 1]);
            }
            m = fmaxf(m, __shfl_xor_sync(0xffffffffu, m, 1));
            m = fmaxf(m, __shfl_xor_sync(0xffffffffu, m, 2));
            if (tig == 0) red[(it * 16 + g + rr * 8) * 16 + warp] = m;
        }
    __syncthreads();
#pragma unroll
    for (int it = 0; it < 2; it++)
#pragma unroll
        for (int rr = 0; rr < 2; rr++) {
            int rowl = it * 16 + g + rr * 8;
            float m = red[rowl * 16];
#pragma unroll
            for (int w = 1; w < 16; w++) m = fmaxf(m, red[rowl * 16 + w]);
            mrow[it][rr] = m;
        }
    __syncthreads();

    // ---- exp + row sum ----
#pragma unroll
    for (int it = 0; it < 2; it++)
#pragma unroll
        for (int rr = 0; rr < 2; rr++) {
            float s = 0.f;
#pragma unroll
            for (int jt = 0; jt < 8; jt++) {
                float p0 = __expf(acc[it][jt][rr * 2]     - mrow[it][rr]);
                float p1 = __expf(acc[it][jt][rr * 2 + 1] - mrow[it][rr]);
                acc[it][jt][rr * 2]     = p0;
                acc[it][jt][rr * 2 + 1] = p1;
                s += p0 + p1;
            }
            s += __shfl_xor_sync(0xffffffffu, s, 1);
            s += __shfl_xor_sync(0xffffffffu, s, 2);
            if (tig == 0) red[(it * 16 + g + rr * 8) * 16 + warp] = s;
        }
    __syncthreads();

    float* Pb = d_P + ((size_t)b * LDIM + i0) * LDIM;
#pragma unroll
    for (int it = 0; it < 2; it++)
#pragma unroll
        for (int rr = 0; rr < 2; rr++) {
            int rowl = it * 16 + g + rr * 8;
            float s = red[rowl * 16];
#pragma unroll
            for (int w = 1; w < 16; w++) s += red[rowl * 16 + w];
            float inv = 1.0f / s;
            float* prow = Pb + (size_t)rowl * LDIM + j0w + 2 * tig;
#pragma unroll
            for (int jt = 0; jt < 8; jt++) {
                float2 o;
                o.x = acc[it][jt][rr * 2] * inv;
                o.y = acc[it][jt][rr * 2 + 1] * inv;
                *(float2*)(prow + jt * 8) = o;
            }
        }
}

// ---------------------------------------------------------------------------
// Kernel 2: V = P @ v^T, SD = P @ std^T, single-pass tf32 mma.
// CTA tile: 128i x 128c. 512 threads = 16 warps (4 wi x 4 wc).
// Warp tile: 32i x 32c = 2 i-tiles x 4 n-tiles per output.
// Operands pre-converted to tf32 (rna) when staged into smem.
// ---------------------------------------------------------------------------
#define T2 512
#define PSTRIDE 36
#define VSTRIDE 136

__global__ void __launch_bounds__(T2)
out_mma_kernel(const float* __restrict__ v, const float* __restrict__ sd,
               float* __restrict__ out) {
    extern __shared__ float smem2[];
    float* ps = smem2;                        // [128][36]
    float* vs = ps + 128 * PSTRIDE;           // [32][136]
    float* ss = vs + 32 * VSTRIDE;            // [32][136]

    const int b    = blockIdx.z;
    const int i0   = blockIdx.x * 128;
    const int c0   = blockIdx.y * 128;
    const int tid  = threadIdx.x;
    const int warp = tid >> 5;
    const int lane = tid & 31;
    const int g    = lane >> 2;
    const int tig  = lane & 3;
    const int wi   = warp & 3;                // i block of 32
    const int wc   = warp >> 2;               // c block of 32

    const float* Pb = d_P + ((size_t)b * LDIM + i0) * LDIM;
    const float* vb = v  + ((size_t)b * CDIM + c0) * LDIM;
    const float* sb = sd + ((size_t)b * CDIM + c0) * LDIM;

    float aV[2][4][4], aS[2][4][4];
#pragma unroll
    for (int it = 0; it < 2; it++)
#pragma unroll
        for (int nt = 0; nt < 4; nt++)
#pragma unroll
            for (int f = 0; f < 4; f++) { aV[it][nt][f] = 0.f; aS[it][nt][f] = 0.f; }

    for (int j0 = 0; j0 < LDIM; j0 += 32) {
        // P tile 128 x 32 (row-major, pre-cvt to tf32)
#pragma unroll
        for (int t = 0; t < 2; t++) {
            int idx = tid + t * T2;
            int i  = idx >> 3;
            int j4 = (idx & 7) << 2;
            float4 p4 = *(const float4*)(Pb + (size_t)i * LDIM + j0 + j4);
            float* dst = ps + i * PSTRIDE + j4;
            dst[0] = __uint_as_float(tf32_rna(p4.x));
            dst[1] = __uint_as_float(tf32_rna(p4.y));
            dst[2] = __uint_as_float(tf32_rna(p4.z));
            dst[3] = __uint_as_float(tf32_rna(p4.w));
        }
        // v / std tiles 128c x 32j -> transposed [j][c], pre-cvt
#pragma unroll
        for (int t = 0; t < 2; t++) {
            int idx = tid + t * T2;
            int c  = idx >> 3;
            int j4 = (idx & 7) << 2;
            float4 t4 = *(const float4*)(vb + (size_t)c * LDIM + j0 + j4);
            vs[(j4 + 0) * VSTRIDE + c] = __uint_as_float(tf32_rna(t4.x));
            vs[(j4 + 1) * VSTRIDE + c] = __uint_as_float(tf32_rna(t4.y));
            vs[(j4 + 2) * VSTRIDE + c] = __uint_as_float(tf32_rna(t4.z));
            vs[(j4 + 3) * VSTRIDE + c] = __uint_as_float(tf32_rna(t4.w));
            float4 u4 = *(const float4*)(sb + (size_t)c * LDIM + j0 + j4);
            ss[(j4 + 0) * VSTRIDE + c] = __uint_as_float(tf32_rna(u4.x));
            ss[(j4 + 1) * VSTRIDE + c] = __uint_as_float(tf32_rna(u4.y));
            ss[(j4 + 2) * VSTRIDE + c] = __uint_as_float(tf32_rna(u4.z));
            ss[(j4 + 3) * VSTRIDE + c] = __uint_as_float(tf32_rna(u4.w));
        }
        __syncthreads();

#pragma unroll
        for (int kk = 0; kk < 32; kk += 8) {
            unsigned au[2][4];
#pragma unroll
            for (int it = 0; it < 2; it++) {
                int base = (wi * 32 + it * 16 + g) * PSTRIDE + kk + tig;
                au[it][0] = __float_as_uint(ps[base]);
                au[it][1] = __float_as_uint(ps[base + 8 * PSTRIDE]);
                au[it][2] = __float_as_uint(ps[base + 4]);
                au[it][3] = __float_as_uint(ps[base + 8 * PSTRIDE + 4]);
            }
#pragma unroll
            for (int nt = 0; nt < 4; nt++) {
                int ncol = wc * 32 + nt * 8 + g;
                unsigned bv0 = __float_as_uint(vs[(kk + tig) * VSTRIDE + ncol]);
                unsigned bv1 = __float_as_uint(vs[(kk + tig + 4) * VSTRIDE + ncol]);
                unsigned bs0 = __float_as_uint(ss[(kk + tig) * VSTRIDE + ncol]);
                unsigned bs1 = __float_as_uint(ss[(kk + tig + 4) * VSTRIDE + ncol]);
#pragma unroll
                for (int it = 0; it < 2; it++) {
                    mma8(aV[it][nt], au[it][0], au[it][1], au[it][2], au[it][3], bv0, bv1);
                    mma8(aS[it][nt], au[it][0], au[it][1], au[it][2], au[it][3], bs0, bs1);
                }
            }
        }
        __syncthreads();
    }

    // epilogue: out[b][c][i] for V, then SD at +B*C*L
    const size_t base  = (size_t)b * CDIM * LDIM;
    const size_t sdoff = (size_t)BATCH * CDIM * LDIM;
#pragma unroll
    for (int it = 0; it < 2; it++)
#pragma unroll
        for (int nt = 0; nt < 4; nt++)
#pragma unroll
            for (int rr = 0; rr < 2; rr++) {
                int i = i0 + wi * 32 + it * 16 + g + rr * 8;
#pragma unroll
                for (int ff = 0; ff < 2; ff++) {
                    int c = c0 + wc * 32 + nt * 8 + 2 * tig + ff;
                    size_t o = base + (size_t)c * LDIM + i;
                    out[o]         = aV[it][nt][rr * 2 + ff];
                    out[o + sdoff] = aS[it][nt][rr * 2 + ff];
                }
            }
}

// ---------------------------------------------------------------------------
extern "C" void kernel_launch(void* const* d_in, const int* in_sizes, int n_in,
                              void* d_out, int out_size) {
    const float* q     = (const float*)d_in[0];
    const float* k     = (const float*)d_in[1];
    const float* v     = (const float*)d_in[2];
    const float* sd    = (const float*)d_in[3];
    const float* table = (const float*)d_in[4];
    const int*   ridx  = (const int*)d_in[5];
    float* out = (float*)d_out;

    const int smem1 = (32 * KSTRIDE + 32 * QSTRIDE + 32 * 16) * (int)sizeof(float); // ~139 KB
    const int smem2 = (128 * PSTRIDE + 2 * 32 * VSTRIDE) * (int)sizeof(float);      // ~53 KB
    cudaFuncSetAttribute(scores_mma_kernel, cudaFuncAttributeMaxDynamicSharedMemorySize, smem1);
    cudaFuncSetAttribute(out_mma_kernel,    cudaFuncAttributeMaxDynamicSharedMemorySize, smem2);

    bias_kernel<<<(LDIM * LDIM) / 256, 256>>>(table, ridx);
    scores_mma_kernel<<<dim3(LDIM / 32, BATCH), T1, smem1>>>(q, k);
    out_mma_kernel<<<dim3(LDIM / 128, CDIM / 128, BATCH), T2, smem2>>>(v, sd, out);
}

// round 4
// speedup vs baseline: 1.7665x; 1.0104x over previous
#include <cuda_runtime.h>

#define BATCH 32
#define CDIM  256
#define LDIM  1024

// Scratch: softmax probabilities P[B][L][L] fp32 (128 MiB) + dense bias [L][L].
__device__ float d_P[(size_t)BATCH * LDIM * LDIM];
__device__ float d_bias[(size_t)LDIM * LDIM];

// ---------------------------------------------------------------------------
// tf32 mma.sync helpers
// ---------------------------------------------------------------------------
__device__ __forceinline__ void mma8(float* c,
                                     unsigned a0, unsigned a1, unsigned a2, unsigned a3,
                                     unsigned b0, unsigned b1) {
    asm volatile(
        "mma.sync.aligned.m16n8k8.row.col.f32.tf32.tf32.f32 "
        "{%0,%1,%2,%3}, {%4,%5,%6,%7}, {%8,%9}, {%0,%1,%2,%3};\n"
        : "+f"(c[0]), "+f"(c[1]), "+f"(c[2]), "+f"(c[3])
        : "r"(a0), "r"(a1), "r"(a2), "r"(a3), "r"(b0), "r"(b1));
}

__device__ __forceinline__ unsigned tf32_hi(float x) {
    return __float_as_uint(x) & 0xffffe000u;
}
__device__ __forceinline__ unsigned tf32_lo(float x, unsigned hi) {
    return __float_as_uint(x - __uint_as_float(hi));
}
__device__ __forceinline__ unsigned tf32_rna(float x) {
    unsigned r;
    asm("cvt.rna.tf32.f32 %0, %1;" : "=r"(r) : "f"(x));
    return r;
}

// ---------------------------------------------------------------------------
// Kernel 0: expand bias_table[rel_index] -> dense [L,L]
// ---------------------------------------------------------------------------
__global__ void bias_kernel(const float* __restrict__ table,
                            const int* __restrict__ ridx) {
    int i = blockIdx.x * blockDim.x + threadIdx.x;
    d_bias[i] = table[ridx[i]];
}

// ---------------------------------------------------------------------------
// Kernel 1: scores = Q^T K + bias (tf32x3 split), softmax over j, write P.
// CTA: 32 i-rows x 1024 j (full row). 512 threads = 16 warps.
// Warp tile: 32i x 64j = 2 i-tiles x 8 j-tiles of m16n8. C chunked by 32.
// smem: ks[32][1032] (pad so B-frag LDS conflict-free), qs[32][36].
// ---------------------------------------------------------------------------
#define T1 512
#define KSTRIDE 1032
#define QSTRIDE 36

__global__ void __launch_bounds__(T1)
scores_mma_kernel(const float* __restrict__ q, const float* __restrict__ k) {
    extern __shared__ float smem[];
    float* ks  = smem;                       // [32][1032]
    float* qs  = smem + 32 * KSTRIDE;        // [32][36]
    float* red = qs + 32 * QSTRIDE;          // [32][16]

    const int b    = blockIdx.y;
    const int i0   = blockIdx.x * 32;
    const int tid  = threadIdx.x;
    const int warp = tid >> 5;
    const int lane = tid & 31;
    const int g    = lane >> 2;              // group row 0..7
    const int tig  = lane & 3;               // thread-in-group
    const int j0w  = warp * 64;

    const float* qb = q + (size_t)b * CDIM * LDIM;
    const float* kb = k + (size_t)b * CDIM * LDIM;

    float acc[2][8][4];
#pragma unroll
    for (int it = 0; it < 2; it++)
#pragma unroll
        for (int jt = 0; jt < 8; jt++)
#pragma unroll
            for (int f = 0; f < 4; f++) acc[it][jt][f] = 0.f;

    for (int c0 = 0; c0 < CDIM; c0 += 32) {
        // K chunk [32][1024] -> ks, coalesced float4
#pragma unroll
        for (int t = 0; t < 16; t++) {
            int idx = tid + t * T1;
            int row = idx >> 8;
            int col = (idx & 255) << 2;
            *(float4*)(ks + row * KSTRIDE + col) =
                *(const float4*)(kb + (size_t)(c0 + row) * LDIM + col);
        }
        // Q chunk: qs[r][cc] = q[c0+cc][i0+r]
#pragma unroll
        for (int t = 0; t < 2; t++) {
            int idx = tid + t * T1;
            int cc = idx >> 5;
            int r  = idx & 31;
            qs[r * QSTRIDE + cc] = qb[(size_t)(c0 + cc) * LDIM + i0 + r];
        }
        __syncthreads();

#pragma unroll
        for (int kk = 0; kk < 32; kk += 8) {
            // A fragments (hi/lo split)
            unsigned ah[2][4], al[2][4];
#pragma unroll
            for (int it = 0; it < 2; it++) {
                int base = (it * 16 + g) * QSTRIDE + kk + tig;
                float a0 = qs[base];
                float a1 = qs[base + 8 * QSTRIDE];
                float a2 = qs[base + 4];
                float a3 = qs[base + 8 * QSTRIDE + 4];
                ah[it][0] = tf32_hi(a0); al[it][0] = tf32_lo(a0, ah[it][0]);
                ah[it][1] = tf32_hi(a1); al[it][1] = tf32_lo(a1, ah[it][1]);
                ah[it][2] = tf32_hi(a2); al[it][2] = tf32_lo(a2, ah[it][2]);
                ah[it][3] = tf32_hi(a3); al[it][3] = tf32_lo(a3, ah[it][3]);
            }
#pragma unroll
            for (int jt = 0; jt < 8; jt++) {
                int jcol = j0w + jt * 8 + g;
                float b0 = ks[(kk + tig) * KSTRIDE + jcol];
                float b1 = ks[(kk + tig + 4) * KSTRIDE + jcol];
                unsigned bh0 = tf32_hi(b0), bh1 = tf32_hi(b1);
                unsigned bl0 = tf32_lo(b0, bh0), bl1 = tf32_lo(b1, bh1);
#pragma unroll
                for (int it = 0; it < 2; it++) {
                    mma8(acc[it][jt], ah[it][0], ah[it][1], ah[it][2], ah[it][3], bh0, bh1);
                    mma8(acc[it][jt], ah[it][0], ah[it][1], ah[it][2], ah[it][3], bl0, bl1);
                    mma8(acc[it][jt], al[it][0], al[it][1], al[it][2], al[it][3], bh0, bh1);
                }
            }
        }
        __syncthreads();
    }

    // ---- add bias ----
#pragma unroll
    for (int it = 0; it < 2; it++)
#pragma unroll
        for (int rr = 0; rr < 2; rr++) {
            int rowl = it * 16 + g + rr * 8;
            const float* brow = d_bias + (size_t)(i0 + rowl) * LDIM + j0w + 2 * tig;
#pragma unroll
            for (int jt = 0; jt < 8; jt++) {
                float2 bv = *(const float2*)(brow + jt * 8);
                acc[it][jt][rr * 2]     += bv.x;
                acc[it][jt][rr * 2 + 1] += bv.y;
            }
        }

    // ---- row max over full 1024 j (16 warps share rows) ----
    float mrow[2][2];
#pragma unroll
    for (int it = 0; it < 2; it++)
#pragma unroll
        for (int rr = 0; rr < 2; rr++) {
            float m = -3.4e38f;
#pragma unroll
            for (int jt = 0; jt < 8; jt++) {
                m = fmaxf(m, acc[it][jt][rr * 2]);
                m = fmaxf(m, acc[it][jt][rr * 2 + 1]);
            }
            m = fmaxf(m, __shfl_xor_sync(0xffffffffu, m, 1));
            m = fmaxf(m, __shfl_xor_sync(0xffffffffu, m, 2));
            if (tig == 0) red[(it * 16 + g + rr * 8) * 16 + warp] = m;
        }
    __syncthreads();
#pragma unroll
    for (int it = 0; it < 2; it++)
#pragma unroll
        for (int rr = 0; rr < 2; rr++) {
            int rowl = it * 16 + g + rr * 8;
            float m = red[rowl * 16];
#pragma unroll
            for (int w = 1; w < 16; w++) m = fmaxf(m, red[rowl * 16 + w]);
            mrow[it][rr] = m;
        }
    __syncthreads();

    // ---- exp + row sum ----
#pragma unroll
    for (int it = 0; it < 2; it++)
#pragma unroll
        for (int rr = 0; rr < 2; rr++) {
            float s = 0.f;
#pragma unroll
            for (int jt = 0; jt < 8; jt++) {
                float p0 = __expf(acc[it][jt][rr * 2]     - mrow[it][rr]);
                float p1 = __expf(acc[it][jt][rr * 2 + 1] - mrow[it][rr]);
                acc[it][jt][rr * 2]     = p0;
                acc[it][jt][rr * 2 + 1] = p1;
                s += p0 + p1;
            }
            s += __shfl_xor_sync(0xffffffffu, s, 1);
            s += __shfl_xor_sync(0xffffffffu, s, 2);
            if (tig == 0) red[(it * 16 + g + rr * 8) * 16 + warp] = s;
        }
    __syncthreads();

    float* Pb = d_P + ((size_t)b * LDIM + i0) * LDIM;
#pragma unroll
    for (int it = 0; it < 2; it++)
#pragma unroll
        for (int rr = 0; rr < 2; rr++) {
            int rowl = it * 16 + g + rr * 8;
            float s = red[rowl * 16];
#pragma unroll
            for (int w = 1; w < 16; w++) s += red[rowl * 16 + w];
            float inv = 1.0f / s;
            float* prow = Pb + (size_t)rowl * LDIM + j0w + 2 * tig;
#pragma unroll
            for (int jt = 0; jt < 8; jt++) {
                float2 o;
                o.x = acc[it][jt][rr * 2] * inv;
                o.y = acc[it][jt][rr * 2 + 1] * inv;
                *(float2*)(prow + jt * 8) = o;
            }
        }
}

// ---------------------------------------------------------------------------
// Kernel 2: V = P @ v^T, SD = P @ std^T, single-pass tf32 mma.
// CTA tile: 128i x 128c. 512 threads = 16 warps (4 wi x 4 wc).
// Warp tile: 32i x 32c = 2 i-tiles x 4 n-tiles per output.
// Operands pre-converted to tf32 (rna) when staged into smem.
// ---------------------------------------------------------------------------
#define T2 512
#define PSTRIDE 36
#define VSTRIDE 136

__global__ void __launch_bounds__(T2)
out_mma_kernel(const float* __restrict__ v, const float* __restrict__ sd,
               float* __restrict__ out) {
    extern __shared__ float smem2[];
    float* ps = smem2;                        // [128][36]
    float* vs = ps + 128 * PSTRIDE;           // [32][136]
    float* ss = vs + 32 * VSTRIDE;            // [32][136]

    const int b    = blockIdx.z;
    const int i0   = blockIdx.x * 128;
    const int c0   = blockIdx.y * 128;
    const int tid  = threadIdx.x;
    const int warp = tid >> 5;
    const int lane = tid & 31;
    const int g    = lane >> 2;
    const int tig  = lane & 3;
    const int wi   = warp & 3;                // i block of 32
    const int wc   = warp >> 2;               // c block of 32

    const float* Pb = d_P + ((size_t)b * LDIM + i0) * LDIM;
    const float* vb = v  + ((size_t)b * CDIM + c0) * LDIM;
    const float* sb = sd + ((size_t)b * CDIM + c0) * LDIM;

    float aV[2][4][4], aS[2][4][4];
#pragma unroll
    for (int it = 0; it < 2; it++)
#pragma unroll
        for (int nt = 0; nt < 4; nt++)
#pragma unroll
            for (int f = 0; f < 4; f++) { aV[it][nt][f] = 0.f; aS[it][nt][f] = 0.f; }

    for (int j0 = 0; j0 < LDIM; j0 += 32) {
        // P tile 128 x 32 (row-major, pre-cvt to tf32)
#pragma unroll
        for (int t = 0; t < 2; t++) {
            int idx = tid + t * T2;
            int i  = idx >> 3;
            int j4 = (idx & 7) << 2;
            float4 p4 = *(const float4*)(Pb + (size_t)i * LDIM + j0 + j4);
            float* dst = ps + i * PSTRIDE + j4;
            dst[0] = __uint_as_float(tf32_rna(p4.x));
            dst[1] = __uint_as_float(tf32_rna(p4.y));
            dst[2] = __uint_as_float(tf32_rna(p4.z));
            dst[3] = __uint_as_float(tf32_rna(p4.w));
        }
        // v / std tiles 128c x 32j -> transposed [j][c], pre-cvt
#pragma unroll
        for (int t = 0; t < 2; t++) {
            int idx = tid + t * T2;
            int c  = idx >> 3;
            int j4 = (idx & 7) << 2;
            float4 t4 = *(const float4*)(vb + (size_t)c * LDIM + j0 + j4);
            vs[(j4 + 0) * VSTRIDE + c] = __uint_as_float(tf32_rna(t4.x));
            vs[(j4 + 1) * VSTRIDE + c] = __uint_as_float(tf32_rna(t4.y));
            vs[(j4 + 2) * VSTRIDE + c] = __uint_as_float(tf32_rna(t4.z));
            vs[(j4 + 3) * VSTRIDE + c] = __uint_as_float(tf32_rna(t4.w));
            float4 u4 = *(const float4*)(sb + (size_t)c * LDIM + j0 + j4);
            ss[(j4 + 0) * VSTRIDE + c] = __uint_as_float(tf32_rna(u4.x));
            ss[(j4 + 1) * VSTRIDE + c] = __uint_as_float(tf32_rna(u4.y));
            ss[(j4 + 2) * VSTRIDE + c] = __uint_as_float(tf32_rna(u4.z));
            ss[(j4 + 3) * VSTRIDE + c] = __uint_as_float(tf32_rna(u4.w));
        }
        __syncthreads();

#pragma unroll
        for (int kk = 0; kk < 32; kk += 8) {
            unsigned au[2][4];
#pragma unroll
            for (int it = 0; it < 2; it++) {
                int base = (wi * 32 + it * 16 + g) * PSTRIDE + kk + tig;
                au[it][0] = __float_as_uint(ps[base]);
                au[it][1] = __float_as_uint(ps[base + 8 * PSTRIDE]);
                au[it][2] = __float_as_uint(ps[base + 4]);
                au[it][3] = __float_as_uint(ps[base + 8 * PSTRIDE + 4]);
            }
#pragma unroll
            for (int nt = 0; nt < 4; nt++) {
                int ncol = wc * 32 + nt * 8 + g;
                unsigned bv0 = __float_as_uint(vs[(kk + tig) * VSTRIDE + ncol]);
                unsigned bv1 = __float_as_uint(vs[(kk + tig + 4) * VSTRIDE + ncol]);
                unsigned bs0 = __float_as_uint(ss[(kk + tig) * VSTRIDE + ncol]);
                unsigned bs1 = __float_as_uint(ss[(kk + tig + 4) * VSTRIDE + ncol]);
#pragma unroll
                for (int it = 0; it < 2; it++) {
                    mma8(aV[it][nt], au[it][0], au[it][1], au[it][2], au[it][3], bv0, bv1);
                    mma8(aS[it][nt], au[it][0], au[it][1], au[it][2], au[it][3], bs0, bs1);
                }
            }
        }
        __syncthreads();
    }

    // epilogue: out[b][c][i] for V, then SD at +B*C*L
    const size_t base  = (size_t)b * CDIM * LDIM;
    const size_t sdoff = (size_t)BATCH * CDIM * LDIM;
#pragma unroll
    for (int it = 0; it < 2; it++)
#pragma unroll
        for (int nt = 0; nt < 4; nt++)
#pragma unroll
            for (int rr = 0; rr < 2; rr++) {
                int i = i0 + wi * 32 + it * 16 + g + rr * 8;
#pragma unroll
                for (int ff = 0; ff < 2; ff++) {
                    int c = c0 + wc * 32 + nt * 8 + 2 * tig + ff;
                    size_t o = base + (size_t)c * LDIM + i;
                    out[o]         = aV[it][nt][rr * 2 + ff];
                    out[o + sdoff] = aS[it][nt][rr * 2 + ff];
                }
            }
}

// ---------------------------------------------------------------------------
extern "C" void kernel_launch(void* const* d_in, const int* in_sizes, int n_in,
                              void* d_out, int out_size) {
    const float* q     = (const float*)d_in[0];
    const float* k     = (const float*)d_in[1];
    const float* v     = (const float*)d_in[2];
    const float* sd    = (const float*)d_in[3];
    const float* table = (const float*)d_in[4];
    const int*   ridx  = (const int*)d_in[5];
    float* out = (float*)d_out;

    const int smem1 = (32 * KSTRIDE + 32 * QSTRIDE + 32 * 16) * (int)sizeof(float); // ~139 KB
    const int smem2 = (128 * PSTRIDE + 2 * 32 * VSTRIDE) * (int)sizeof(float);      // ~53 KB
    cudaFuncSetAttribute(scores_mma_kernel, cudaFuncAttributeMaxDynamicSharedMemorySize, smem1);
    cudaFuncSetAttribute(out_mma_kernel,    cudaFuncAttributeMaxDynamicSharedMemorySize, smem2);

    bias_kernel<<<(LDIM * LDIM) / 256, 256>>>(table, ridx);
    scores_mma_kernel<<<dim3(LDIM / 32, BATCH), T1, smem1>>>(q, k);
    out_mma_kernel<<<dim3(LDIM / 128, CDIM / 128, BATCH), T2, smem2>>>(v, sd, out);
}